// round 15
// baseline (speedup 1.0000x reference)
#include <cuda_runtime.h>
#include <cuda_fp16.h>
#include <cstdint>
#include <math.h>

#define T 8192
#define H 2048
#define IDIM 2816
#define NE 16
#define R1 128

#define NX   ((size_t)T * H)
#define NUP  ((size_t)NE * 2 * IDIM * H)
#define NDN  ((size_t)NE * H * IDIM)
#define NOUT ((size_t)T * H)

#define BM 128
#define BN 64      // gemm1 N tile (gate; up mirrored)
#define BN2 128    // gemm2 N tile
#define BK 64      // halves per K slab (4 x k16 mma)
#define BKW 36     // padded words per 64-half row (conflict-free phases)
#define NST 3      // pipeline stages (rolling pointer)
#define MAXMT 16   // max m-tiles per expert

// ---------------- device scratch (static) ----------------
__device__ __half g_x16[NX];
__device__ __half g_wup16[NUP];
__device__ __half g_wdn16[NDN];
__device__ float  g_tanh[(size_t)T * R1];
__device__ int    g_list[NE * T];
__device__ float  g_wgt[NE * T];
__device__ int    g_cnt[NE];
__device__ int    g_base[NE];
__device__ int    g_done;
__device__ __half g_h16[(size_t)(2 * T + 128) * IDIM];

// ---------------- helpers ----------------
__device__ __forceinline__ void mma16(float* d, const uint32_t* a, const uint32_t* b) {
    asm volatile(
        "mma.sync.aligned.m16n8k16.row.col.f32.f16.f16.f32 "
        "{%0,%1,%2,%3},{%4,%5,%6,%7},{%8,%9},{%0,%1,%2,%3};\n"
        : "+f"(d[0]), "+f"(d[1]), "+f"(d[2]), "+f"(d[3])
        : "r"(a[0]), "r"(a[1]), "r"(a[2]), "r"(a[3]), "r"(b[0]), "r"(b[1]));
}
__device__ __forceinline__ void ldsm4(uint32_t* r, uint32_t a) {
    asm volatile("ldmatrix.sync.aligned.m8n8.x4.shared.b16 {%0,%1,%2,%3}, [%4];"
        : "=r"(r[0]), "=r"(r[1]), "=r"(r[2]), "=r"(r[3]) : "r"(a));
}
__device__ __forceinline__ void cp16(uint32_t dst, const void* src) {
    asm volatile("cp.async.cg.shared.global [%0], [%1], 16;\n" :: "r"(dst), "l"(src));
}
__device__ __forceinline__ void cpcommit() { asm volatile("cp.async.commit_group;\n" ::); }
__device__ __forceinline__ void cpwait1()  { asm volatile("cp.async.wait_group 1;\n" ::); }

// ---------------- K-cvt: fp32 -> fp16 operands; zero out + counters ----------------
__global__ void __launch_bounds__(256) k_cvt(const float* __restrict__ x,
                                             const float* __restrict__ wup,
                                             const float* __restrict__ wdn,
                                             float* __restrict__ out) {
    if (blockIdx.x == 0 && threadIdx.x < NE) g_cnt[threadIdx.x] = 0;
    const size_t X4 = NX / 4, U4 = NUP / 4, D4 = NDN / 4, O4 = NOUT / 4;
    const size_t NT = X4 + U4 + D4 + O4;
    const size_t stride = (size_t)gridDim.x * blockDim.x;
    for (size_t i = (size_t)blockIdx.x * blockDim.x + threadIdx.x; i < NT; i += stride) {
        const float4* src; __half* dst; size_t off;
        if (i < X4)                { src = (const float4*)x;   dst = g_x16;   off = i; }
        else if (i < X4 + U4)      { src = (const float4*)wup; dst = g_wup16; off = i - X4; }
        else if (i < X4 + U4 + D4) { src = (const float4*)wdn; dst = g_wdn16; off = i - X4 - U4; }
        else { ((float4*)out)[i - X4 - U4 - D4] = make_float4(0.f, 0.f, 0.f, 0.f); continue; }
        float4 v = __ldg(src + off);
        __half2 lo = __floats2half2_rn(v.x, v.y);
        __half2 hi = __floats2half2_rn(v.z, v.w);
        uint2 pk = make_uint2(*(uint32_t*)&lo, *(uint32_t*)&hi);
        *(uint2*)(dst + off * 4) = pk;
    }
}

// ---------------- K1: router layer 1 (fp32 SIMT GEMM + tanh), 64 tokens/block ----------------
__global__ void __launch_bounds__(256) k_router(const float* __restrict__ x,
                                                const float* __restrict__ wg1) {
    __shared__ float As[16][68];
    __shared__ float Bs[16][132];
    const int m0  = blockIdx.x * 64;
    const int tid = threadIdx.x;
    const int r0  = (tid >> 4) * 4;
    const int c0  = (tid & 15) * 8;

    float acc[4][8];
#pragma unroll
    for (int r = 0; r < 4; r++)
#pragma unroll
        for (int c = 0; c < 8; c++) acc[r][c] = 0.f;

    for (int k0 = 0; k0 < H; k0 += 16) {
        {
            int row = tid >> 2, q = tid & 3;
            float4 v = *(const float4*)(x + (size_t)(m0 + row) * H + k0 + q * 4);
            As[q * 4 + 0][row] = v.x; As[q * 4 + 1][row] = v.y;
            As[q * 4 + 2][row] = v.z; As[q * 4 + 3][row] = v.w;
        }
#pragma unroll
        for (int i = 0; i < 2; i++) {
            int lin = tid + i * 256, n = lin >> 2, q = lin & 3;
            float4 v = *(const float4*)(wg1 + (size_t)n * H + k0 + q * 4);
            Bs[q * 4 + 0][n] = v.x; Bs[q * 4 + 1][n] = v.y;
            Bs[q * 4 + 2][n] = v.z; Bs[q * 4 + 3][n] = v.w;
        }
        __syncthreads();
#pragma unroll
        for (int kk = 0; kk < 16; kk++) {
            float a[4], b[8];
            *(float4*)a       = *(const float4*)&As[kk][r0];
            *(float4*)b       = *(const float4*)&Bs[kk][c0];
            *(float4*)(b + 4) = *(const float4*)&Bs[kk][c0 + 4];
#pragma unroll
            for (int r = 0; r < 4; r++)
#pragma unroll
                for (int c = 0; c < 8; c++) acc[r][c] += a[r] * b[c];
        }
        __syncthreads();
    }
#pragma unroll
    for (int r = 0; r < 4; r++)
#pragma unroll
        for (int c = 0; c < 8; c++)
            g_tanh[(size_t)(m0 + r0 + r) * R1 + c0 + c] = tanhf(acc[r][c]);
}

// ---------------- K2: router layer 2 + top-2 + routing tables + prefix ----------------
__global__ void k_topk(const float* __restrict__ wg2) {
    const int tok  = blockIdx.x * 8 + (threadIdx.x >> 5);
    const int lane = threadIdx.x & 31;
    float acc[NE];
#pragma unroll
    for (int e = 0; e < NE; e++) acc[e] = 0.f;
    const float* tv = g_tanh + (size_t)tok * R1;
#pragma unroll
    for (int j = 0; j < 4; j++) {
        float v = tv[lane + 32 * j];
#pragma unroll
        for (int e = 0; e < NE; e++) acc[e] += v * __ldg(&wg2[e * R1 + lane + 32 * j]);
    }
#pragma unroll
    for (int e = 0; e < NE; e++) {
        acc[e] += __shfl_xor_sync(0xffffffffu, acc[e], 16);
        acc[e] += __shfl_xor_sync(0xffffffffu, acc[e], 8);
        acc[e] += __shfl_xor_sync(0xffffffffu, acc[e], 4);
        acc[e] += __shfl_xor_sync(0xffffffffu, acc[e], 2);
        acc[e] += __shfl_xor_sync(0xffffffffu, acc[e], 1);
    }
    if (lane == 0) {
        int i1 = 0; float v1 = acc[0];
#pragma unroll
        for (int e = 1; e < NE; e++) if (acc[e] > v1) { v1 = acc[e]; i1 = e; }
        int i2 = -1; float v2 = -3.4e38f;
#pragma unroll
        for (int e = 0; e < NE; e++) if (e != i1 && acc[e] > v2) { v2 = acc[e]; i2 = e; }
        float w1 = 1.f / (1.f + expf(v2 - v1));
        float w2 = 1.f / (1.f + expf(v1 - v2));
        int s1 = atomicAdd(&g_cnt[i1], 1);
        g_list[i1 * T + s1] = tok; g_wgt[i1 * T + s1] = w1;
        int s2 = atomicAdd(&g_cnt[i2], 1);
        g_list[i2 * T + s2] = tok; g_wgt[i2 * T + s2] = w2;
    }
    __syncthreads();
    if (threadIdx.x == 0) {
        __threadfence();
        int d = atomicAdd(&g_done, 1);
        if (d == gridDim.x - 1) {
            int s = 0;
            for (int e = 0; e < NE; e++) {
                int c = atomicAdd(&g_cnt[e], 0);
                g_base[e] = s; s += c;
            }
            atomicExch(&g_done, 0);
        }
    }
}

// ---------------- K4: fp16 gate+up GEMM fused with SwiGLU (BK=64, 3-stage) ----------------
__global__ void __launch_bounds__(256, 2) k_gemm1() {
    const int e   = blockIdx.z;
    const int cnt = g_cnt[e];
    const int m0  = blockIdx.y * BM;
    if (m0 >= cnt) return;
    const int n0   = blockIdx.x * BN;
    const int base = g_base[e];

    extern __shared__ uint32_t sm[];
    const uint32_t stB = 256 * BKW * 4;    // 36864 B per stage (A 128 + B 128 rows)
    const uint32_t wrapB = NST * stB;

    const int tid  = threadIdx.x;
    const int lane = tid & 31;
    const int warp = tid >> 5;
    const int wm = warp & 3, wn = warp >> 2;
    const int g = lane >> 2, t = lane & 3;
    const int q = tid & 3, r0 = tid >> 2;

    int gr0 = m0 + r0;      if (gr0 > cnt - 1) gr0 = cnt - 1;
    int gr1 = m0 + r0 + 64; if (gr1 > cnt - 1) gr1 = cnt - 1;
    const __half* aSrc0 = g_x16 + (size_t)g_list[e * T + gr0] * H + q * 8;
    const __half* aSrc1 = g_x16 + (size_t)g_list[e * T + gr1] * H + q * 8;
    const __half* wb = g_wup16 + (size_t)e * 2 * IDIM * H;
    const __half* bgSrc = wb + (size_t)(n0 + r0) * H + q * 8;
    const __half* buSrc = wb + (size_t)(IDIM + n0 + r0) * H + q * 8;

    const uint32_t smA = (uint32_t)__cvta_generic_to_shared(sm);
    const uint32_t smB = smA + 128 * BKW * 4;
    uint32_t aDst0 = smA + (r0 * BKW + q * 4) * 4;
    uint32_t aDst1 = smA + ((r0 + 64) * BKW + q * 4) * 4;
    uint32_t bgDst = smB + (r0 * BKW + q * 4) * 4;
    uint32_t buDst = smB + ((64 + r0) * BKW + q * 4) * 4;

    const int l7 = lane & 7;
    const int aRowL = wm * 32 + l7 + ((lane >> 3) & 1) * 8;
    const int aKwL  = (lane >> 4) * 4;
    uint32_t aLd0 = smA + (aRowL * BKW + aKwL) * 4;
    uint32_t aLd1 = aLd0 + 16 * BKW * 4;
    const int bRowL = wn * 32 + l7 + (lane >> 4) * 8;
    const int bKwL  = ((lane >> 3) & 1) * 4;
    uint32_t bg0 = smB + (bRowL * BKW + bKwL) * 4;
    uint32_t bg1 = bg0 + 16 * BKW * 4;
    uint32_t bu0 = bg0 + 64 * BKW * 4;
    uint32_t bu1 = bg1 + 64 * BKW * 4;

    float dg[2][4][4], du[2][4][4];
#pragma unroll
    for (int a = 0; a < 2; a++)
#pragma unroll
        for (int b = 0; b < 4; b++)
#pragma unroll
            for (int c = 0; c < 4; c++) { dg[a][b][c] = 0.f; du[a][b][c] = 0.f; }

#define G1_LOAD(so, k0)                                                        \
    {                                                                          \
        cp16(aDst0 + (so), aSrc0 + (k0)); cp16(aDst0 + (so) + 64, aSrc0 + (k0) + 32); \
        cp16(aDst1 + (so), aSrc1 + (k0)); cp16(aDst1 + (so) + 64, aSrc1 + (k0) + 32); \
        cp16(bgDst + (so), bgSrc + (k0)); cp16(bgDst + (so) + 64, bgSrc + (k0) + 32); \
        cp16(buDst + (so), buSrc + (k0)); cp16(buDst + (so) + 64, buSrc + (k0) + 32); \
    }

    const int NK = H / BK;  // 32
    G1_LOAD(0, 0); cpcommit();
    G1_LOAD(stB, BK); cpcommit();
    cpwait1();
    __syncthreads();

    uint32_t soC = 0, soL = 2 * stB;
    int kL = 2 * BK;

    for (int it = 0; it < NK; ++it) {
        if (it + 2 < NK) G1_LOAD(soL, kL);
        cpcommit();

#pragma unroll
        for (int ks = 0; ks < 4; ks++) {
            const uint32_t ko = soC + ks * 32;  // 8 words per k16
            uint32_t af0[4], af1[4], bf[4];
            ldsm4(af0, aLd0 + ko);
            ldsm4(af1, aLd1 + ko);
            ldsm4(bf, bg0 + ko);
            mma16(dg[0][0], af0, bf);     mma16(dg[1][0], af1, bf);
            mma16(dg[0][1], af0, bf + 2); mma16(dg[1][1], af1, bf + 2);
            ldsm4(bf, bg1 + ko);
            mma16(dg[0][2], af0, bf);     mma16(dg[1][2], af1, bf);
            mma16(dg[0][3], af0, bf + 2); mma16(dg[1][3], af1, bf + 2);
            ldsm4(bf, bu0 + ko);
            mma16(du[0][0], af0, bf);     mma16(du[1][0], af1, bf);
            mma16(du[0][1], af0, bf + 2); mma16(du[1][1], af1, bf + 2);
            ldsm4(bf, bu1 + ko);
            mma16(du[0][2], af0, bf);     mma16(du[1][2], af1, bf);
            mma16(du[0][3], af0, bf + 2); mma16(du[1][3], af1, bf + 2);
        }

        cpwait1();
        __syncthreads();
        soC += stB; if (soC == wrapB) soC = 0;
        soL += stB; if (soL == wrapB) soL = 0;
        kL += BK;
    }
#undef G1_LOAD

    // epilogue: SwiGLU -> g_h16
#pragma unroll
    for (int mi = 0; mi < 2; mi++) {
#pragma unroll
        for (int p = 0; p < 2; p++) {
            int rl = wm * 32 + mi * 16 + g + p * 8;
            if (m0 + rl < cnt) {
                size_t rb = (size_t)(base + m0 + rl) * IDIM + n0;
#pragma unroll
                for (int ni = 0; ni < 4; ni++) {
                    int col = wn * 32 + ni * 8 + t * 2;
                    float g0 = dg[mi][ni][p * 2], g1 = dg[mi][ni][p * 2 + 1];
                    float u0 = du[mi][ni][p * 2], u1 = du[mi][ni][p * 2 + 1];
                    float h0 = g0 / (1.f + expf(-g0)) * u0;
                    float h1 = g1 / (1.f + expf(-g1)) * u1;
                    __half2 hv = __floats2half2_rn(h0, h1);
                    *(__half2*)(g_h16 + rb + col) = hv;
                }
            }
        }
    }
}

// ---------------- K5: fp16 down GEMM (BN2=128, BK=64, 3-stage) + atomic combine ----------------
__global__ void __launch_bounds__(256, 2) k_gemm2(float* __restrict__ out) {
    const int e   = blockIdx.z;
    const int cnt = g_cnt[e];
    const int m0  = blockIdx.y * BM;
    if (m0 >= cnt) return;
    const int n0   = blockIdx.x * BN2;
    const int base = g_base[e];

    extern __shared__ uint32_t sm[];
    const uint32_t stB = 256 * BKW * 4;
    const uint32_t wrapB = NST * stB;

    const int tid  = threadIdx.x;
    const int lane = tid & 31;
    const int warp = tid >> 5;
    const int wm = warp & 3, wn = warp >> 2;
    const int g = lane >> 2, t = lane & 3;
    const int q = tid & 3, r0 = tid >> 2;

    int gr0 = m0 + r0;      if (gr0 > cnt - 1) gr0 = cnt - 1;
    int gr1 = m0 + r0 + 64; if (gr1 > cnt - 1) gr1 = cnt - 1;
    const __half* aSrc0 = g_h16 + (size_t)(base + gr0) * IDIM + q * 8;
    const __half* aSrc1 = g_h16 + (size_t)(base + gr1) * IDIM + q * 8;
    const __half* wb = g_wdn16 + (size_t)e * H * IDIM;
    const __half* bSrc0 = wb + (size_t)(n0 + r0) * IDIM + q * 8;
    const __half* bSrc1 = wb + (size_t)(n0 + 64 + r0) * IDIM + q * 8;

    const uint32_t smA = (uint32_t)__cvta_generic_to_shared(sm);
    const uint32_t smB = smA + 128 * BKW * 4;
    uint32_t aDst0 = smA + (r0 * BKW + q * 4) * 4;
    uint32_t aDst1 = smA + ((r0 + 64) * BKW + q * 4) * 4;
    uint32_t bDst0 = smB + (r0 * BKW + q * 4) * 4;
    uint32_t bDst1 = smB + ((r0 + 64) * BKW + q * 4) * 4;

    const int l7 = lane & 7;
    const int aRowL = wm * 32 + l7 + ((lane >> 3) & 1) * 8;
    const int aKwL  = (lane >> 4) * 4;
    uint32_t aLd0 = smA + (aRowL * BKW + aKwL) * 4;
    uint32_t aLd1 = aLd0 + 16 * BKW * 4;
    const int bRowL = wn * 64 + l7 + (lane >> 4) * 8;
    const int bKwL  = ((lane >> 3) & 1) * 4;
    uint32_t b0 = smB + (bRowL * BKW + bKwL) * 4;
    uint32_t b1 = b0 + 16 * BKW * 4;
    uint32_t b2 = b0 + 32 * BKW * 4;
    uint32_t b3 = b0 + 48 * BKW * 4;

    float d[2][8][4];
#pragma unroll
    for (int a = 0; a < 2; a++)
#pragma unroll
        for (int b = 0; b < 8; b++)
#pragma unroll
            for (int c = 0; c < 4; c++) d[a][b][c] = 0.f;

#define G2_LOAD(so, k0)                                                        \
    {                                                                          \
        cp16(aDst0 + (so), aSrc0 + (k0)); cp16(aDst0 + (so) + 64, aSrc0 + (k0) + 32); \
        cp16(aDst1 + (so), aSrc1 + (k0)); cp16(aDst1 + (so) + 64, aSrc1 + (k0) + 32); \
        cp16(bDst0 + (so), bSrc0 + (k0)); cp16(bDst0 + (so) + 64, bSrc0 + (k0) + 32); \
        cp16(bDst1 + (so), bSrc1 + (k0)); cp16(bDst1 + (so) + 64, bSrc1 + (k0) + 32); \
    }

    const int NK = IDIM / BK;  // 44
    G2_LOAD(0, 0); cpcommit();
    G2_LOAD(stB, BK); cpcommit();
    cpwait1();
    __syncthreads();

    uint32_t soC = 0, soL = 2 * stB;
    int kL = 2 * BK;

    for (int it = 0; it < NK; ++it) {
        if (it + 2 < NK) G2_LOAD(soL, kL);
        cpcommit();

#pragma unroll
        for (int ks = 0; ks < 4; ks++) {
            const uint32_t ko = soC + ks * 32;
            uint32_t af0[4], af1[4], bf[4];
            ldsm4(af0, aLd0 + ko);
            ldsm4(af1, aLd1 + ko);
            ldsm4(bf, b0 + ko);
            mma16(d[0][0], af0, bf);     mma16(d[1][0], af1, bf);
            mma16(d[0][1], af0, bf + 2); mma16(d[1][1], af1, bf + 2);
            ldsm4(bf, b1 + ko);
            mma16(d[0][2], af0, bf);     mma16(d[1][2], af1, bf);
            mma16(d[0][3], af0, bf + 2); mma16(d[1][3], af1, bf + 2);
            ldsm4(bf, b2 + ko);
            mma16(d[0][4], af0, bf);     mma16(d[1][4], af1, bf);
            mma16(d[0][5], af0, bf + 2); mma16(d[1][5], af1, bf + 2);
            ldsm4(bf, b3 + ko);
            mma16(d[0][6], af0, bf);     mma16(d[1][6], af1, bf);
            mma16(d[0][7], af0, bf + 2); mma16(d[1][7], af1, bf + 2);
        }

        cpwait1();
        __syncthreads();
        soC += stB; if (soC == wrapB) soC = 0;
        soL += stB; if (soL == wrapB) soL = 0;
        kL += BK;
    }
#undef G2_LOAD

#pragma unroll
    for (int mi = 0; mi < 2; mi++) {
#pragma unroll
        for (int p = 0; p < 2; p++) {
            int rl = wm * 32 + mi * 16 + g + p * 8;
            if (m0 + rl < cnt) {
                int tok = g_list[e * T + m0 + rl];
                float w = g_wgt[e * T + m0 + rl];
                float* op = out + (size_t)tok * H + n0 + wn * 64;
#pragma unroll
                for (int ni = 0; ni < 8; ni++) {
                    int col = ni * 8 + t * 2;
                    atomicAdd(op + col,     w * d[mi][ni][p * 2]);
                    atomicAdd(op + col + 1, w * d[mi][ni][p * 2 + 1]);
                }
            }
        }
    }
}

// ---------------- launch ----------------
extern "C" void kernel_launch(void* const* d_in, const int* in_sizes, int n_in,
                              void* d_out, int out_size) {
    const float* x      = (const float*)d_in[0];
    const float* wg1    = (const float*)d_in[1];
    const float* wg2    = (const float*)d_in[2];
    const float* w_up   = (const float*)d_in[3];
    const float* w_down = (const float*)d_in[4];
    float* out = (float*)d_out;

    const int smem = NST * 256 * BKW * 4;   // 110592
    cudaFuncSetAttribute(k_gemm1, cudaFuncAttributeMaxDynamicSharedMemorySize, smem);
    cudaFuncSetAttribute(k_gemm2, cudaFuncAttributeMaxDynamicSharedMemorySize, smem);

    k_cvt<<<1184, 256>>>(x, w_up, w_down, out);                 // 1
    k_router<<<T / 64, 256>>>(x, wg1);                          // 2
    k_topk<<<T / 8, 256>>>(wg2);                                // 3 (incl. prefix)
    k_gemm1<<<dim3(IDIM / BN, MAXMT, NE), 256, smem>>>();       // 4 (ncu slot)
    k_gemm2<<<dim3(H / BN2, MAXMT, NE), 256, smem>>>(out);      // 5
}

// round 16
// speedup vs baseline: 1.0776x; 1.0776x over previous
#include <cuda_runtime.h>
#include <cuda_fp16.h>
#include <cstdint>
#include <math.h>

#define T 8192
#define H 2048
#define IDIM 2816
#define NE 16
#define R1 128

#define NX   ((size_t)T * H)
#define NUP  ((size_t)NE * 2 * IDIM * H)
#define NDN  ((size_t)NE * H * IDIM)
#define NOUT ((size_t)T * H)

#define BM 128
#define BN 64      // gemm1 N tile (gate; up mirrored)
#define BN2 128    // gemm2 N tile
#define BK 32      // halves per K slab (2 x k16 mma)
#define BKW 20     // padded words per 32-half row (conflict-free LDSM phases)
#define NST 4      // pipeline stages
#define MAXMT 16   // max m-tiles per expert (2048 tokens; counts are 1024±31)

// ---------------- device scratch (static) ----------------
__device__ __half g_x16[NX];
__device__ __half g_wup16[NUP];
__device__ __half g_wdn16[NDN];
__device__ float  g_tanh[(size_t)T * R1];
__device__ int    g_list[NE * T];
__device__ float  g_wgt[NE * T];
__device__ int    g_cnt[NE];
__device__ int    g_base[NE];
__device__ int    g_done;
__device__ __half g_h16[(size_t)(2 * T + 128) * IDIM];

// ---------------- helpers ----------------
__device__ __forceinline__ void mma16(float* d, const uint32_t* a, const uint32_t* b) {
    asm volatile(
        "mma.sync.aligned.m16n8k16.row.col.f32.f16.f16.f32 "
        "{%0,%1,%2,%3},{%4,%5,%6,%7},{%8,%9},{%0,%1,%2,%3};\n"
        : "+f"(d[0]), "+f"(d[1]), "+f"(d[2]), "+f"(d[3])
        : "r"(a[0]), "r"(a[1]), "r"(a[2]), "r"(a[3]), "r"(b[0]), "r"(b[1]));
}
__device__ __forceinline__ void ldsm4(uint32_t* r, uint32_t a) {
    asm volatile("ldmatrix.sync.aligned.m8n8.x4.shared.b16 {%0,%1,%2,%3}, [%4];"
        : "=r"(r[0]), "=r"(r[1]), "=r"(r[2]), "=r"(r[3]) : "r"(a));
}
__device__ __forceinline__ void cp16(uint32_t dst, const void* src) {
    asm volatile("cp.async.cg.shared.global [%0], [%1], 16;\n" :: "r"(dst), "l"(src));
}
__device__ __forceinline__ void cpcommit() { asm volatile("cp.async.commit_group;\n" ::); }
__device__ __forceinline__ void cpwait2()  { asm volatile("cp.async.wait_group 2;\n" ::); }

// ---------------- K-cvt: fp32 -> fp16 operands (8 floats/iter); zero out + counters ----------------
__global__ void __launch_bounds__(256) k_cvt(const float* __restrict__ x,
                                             const float* __restrict__ wup,
                                             const float* __restrict__ wdn,
                                             float* __restrict__ out) {
    if (blockIdx.x == 0 && threadIdx.x < NE) g_cnt[threadIdx.x] = 0;
    const size_t X8 = NX / 8, U8 = NUP / 8, D8 = NDN / 8, O8 = NOUT / 8;
    const size_t NT = X8 + U8 + D8 + O8;
    const size_t stride = (size_t)gridDim.x * blockDim.x;
    for (size_t i = (size_t)blockIdx.x * blockDim.x + threadIdx.x; i < NT; i += stride) {
        const float4* src; __half* dst; size_t off;
        if (i < X8)                { src = (const float4*)x;   dst = g_x16;   off = i; }
        else if (i < X8 + U8)      { src = (const float4*)wup; dst = g_wup16; off = i - X8; }
        else if (i < X8 + U8 + D8) { src = (const float4*)wdn; dst = g_wdn16; off = i - X8 - U8; }
        else {
            size_t o = (i - X8 - U8 - D8) * 2;
            float4 z = make_float4(0.f, 0.f, 0.f, 0.f);
            ((float4*)out)[o] = z; ((float4*)out)[o + 1] = z;
            continue;
        }
        float4 v0 = __ldg(src + off * 2);
        float4 v1 = __ldg(src + off * 2 + 1);
        __half2 a = __floats2half2_rn(v0.x, v0.y);
        __half2 b = __floats2half2_rn(v0.z, v0.w);
        __half2 c = __floats2half2_rn(v1.x, v1.y);
        __half2 d = __floats2half2_rn(v1.z, v1.w);
        uint4 pk = make_uint4(*(uint32_t*)&a, *(uint32_t*)&b, *(uint32_t*)&c, *(uint32_t*)&d);
        *(uint4*)(dst + off * 8) = pk;
    }
}

// ---------------- K1: router layer 1 (fp32 SIMT GEMM + tanh), 64 tokens/block ----------------
__global__ void __launch_bounds__(256) k_router(const float* __restrict__ x,
                                                const float* __restrict__ wg1) {
    __shared__ float As[16][68];
    __shared__ float Bs[16][132];
    const int m0  = blockIdx.x * 64;
    const int tid = threadIdx.x;
    const int r0  = (tid >> 4) * 4;
    const int c0  = (tid & 15) * 8;

    float acc[4][8];
#pragma unroll
    for (int r = 0; r < 4; r++)
#pragma unroll
        for (int c = 0; c < 8; c++) acc[r][c] = 0.f;

    for (int k0 = 0; k0 < H; k0 += 16) {
        {
            int row = tid >> 2, q = tid & 3;
            float4 v = *(const float4*)(x + (size_t)(m0 + row) * H + k0 + q * 4);
            As[q * 4 + 0][row] = v.x; As[q * 4 + 1][row] = v.y;
            As[q * 4 + 2][row] = v.z; As[q * 4 + 3][row] = v.w;
        }
#pragma unroll
        for (int i = 0; i < 2; i++) {
            int lin = tid + i * 256, n = lin >> 2, q = lin & 3;
            float4 v = *(const float4*)(wg1 + (size_t)n * H + k0 + q * 4);
            Bs[q * 4 + 0][n] = v.x; Bs[q * 4 + 1][n] = v.y;
            Bs[q * 4 + 2][n] = v.z; Bs[q * 4 + 3][n] = v.w;
        }
        __syncthreads();
#pragma unroll
        for (int kk = 0; kk < 16; kk++) {
            float a[4], b[8];
            *(float4*)a       = *(const float4*)&As[kk][r0];
            *(float4*)b       = *(const float4*)&Bs[kk][c0];
            *(float4*)(b + 4) = *(const float4*)&Bs[kk][c0 + 4];
#pragma unroll
            for (int r = 0; r < 4; r++)
#pragma unroll
                for (int c = 0; c < 8; c++) acc[r][c] += a[r] * b[c];
        }
        __syncthreads();
    }
#pragma unroll
    for (int r = 0; r < 4; r++)
#pragma unroll
        for (int c = 0; c < 8; c++)
            g_tanh[(size_t)(m0 + r0 + r) * R1 + c0 + c] = tanhf(acc[r][c]);
}

// ---------------- K2: router layer 2 + top-2 + routing tables + prefix ----------------
__global__ void k_topk(const float* __restrict__ wg2) {
    const int tok  = blockIdx.x * 8 + (threadIdx.x >> 5);
    const int lane = threadIdx.x & 31;
    float acc[NE];
#pragma unroll
    for (int e = 0; e < NE; e++) acc[e] = 0.f;
    const float* tv = g_tanh + (size_t)tok * R1;
#pragma unroll
    for (int j = 0; j < 4; j++) {
        float v = tv[lane + 32 * j];
#pragma unroll
        for (int e = 0; e < NE; e++) acc[e] += v * __ldg(&wg2[e * R1 + lane + 32 * j]);
    }
#pragma unroll
    for (int e = 0; e < NE; e++) {
        acc[e] += __shfl_xor_sync(0xffffffffu, acc[e], 16);
        acc[e] += __shfl_xor_sync(0xffffffffu, acc[e], 8);
        acc[e] += __shfl_xor_sync(0xffffffffu, acc[e], 4);
        acc[e] += __shfl_xor_sync(0xffffffffu, acc[e], 2);
        acc[e] += __shfl_xor_sync(0xffffffffu, acc[e], 1);
    }
    if (lane == 0) {
        int i1 = 0; float v1 = acc[0];
#pragma unroll
        for (int e = 1; e < NE; e++) if (acc[e] > v1) { v1 = acc[e]; i1 = e; }
        int i2 = -1; float v2 = -3.4e38f;
#pragma unroll
        for (int e = 0; e < NE; e++) if (e != i1 && acc[e] > v2) { v2 = acc[e]; i2 = e; }
        float w1 = 1.f / (1.f + expf(v2 - v1));
        float w2 = 1.f / (1.f + expf(v1 - v2));
        int s1 = atomicAdd(&g_cnt[i1], 1);
        g_list[i1 * T + s1] = tok; g_wgt[i1 * T + s1] = w1;
        int s2 = atomicAdd(&g_cnt[i2], 1);
        g_list[i2 * T + s2] = tok; g_wgt[i2 * T + s2] = w2;
    }
    __syncthreads();
    if (threadIdx.x == 0) {
        __threadfence();
        int d = atomicAdd(&g_done, 1);
        if (d == gridDim.x - 1) {
            int s = 0;
            for (int e = 0; e < NE; e++) {
                int c = atomicAdd(&g_cnt[e], 0);
                g_base[e] = s; s += c;
            }
            atomicExch(&g_done, 0);
        }
    }
}

// ---------------- K4: fp16 gate+up GEMM fused with SwiGLU (R14 body) ----------------
__global__ void __launch_bounds__(256, 2) k_gemm1() {
    const int e   = blockIdx.z;
    const int cnt = g_cnt[e];
    const int m0  = blockIdx.y * BM;
    if (m0 >= cnt) return;
    const int n0   = blockIdx.x * BN;
    const int base = g_base[e];

    extern __shared__ uint32_t sm[];
    const int STW = 2 * 128 * BKW;
    const uint32_t stB = STW * 4;

    const int tid  = threadIdx.x;
    const int lane = tid & 31;
    const int warp = tid >> 5;
    const int wm = warp & 3, wn = warp >> 2;
    const int g = lane >> 2, t = lane & 3;
    const int q = tid & 3, r0 = tid >> 2;

    int gr0 = m0 + r0;      if (gr0 > cnt - 1) gr0 = cnt - 1;
    int gr1 = m0 + r0 + 64; if (gr1 > cnt - 1) gr1 = cnt - 1;
    const __half* aSrc0 = g_x16 + (size_t)g_list[e * T + gr0] * H + q * 8;
    const __half* aSrc1 = g_x16 + (size_t)g_list[e * T + gr1] * H + q * 8;
    const __half* wb = g_wup16 + (size_t)e * 2 * IDIM * H;
    const __half* bgSrc = wb + (size_t)(n0 + r0) * H + q * 8;
    const __half* buSrc = wb + (size_t)(IDIM + n0 + r0) * H + q * 8;

    const uint32_t smA = (uint32_t)__cvta_generic_to_shared(sm);
    const uint32_t smB = smA + 128 * BKW * 4;
    uint32_t aDst0 = smA + (r0 * BKW + q * 4) * 4;
    uint32_t aDst1 = smA + ((r0 + 64) * BKW + q * 4) * 4;
    uint32_t bgDst = smB + (r0 * BKW + q * 4) * 4;
    uint32_t buDst = smB + ((64 + r0) * BKW + q * 4) * 4;

    const int l7 = lane & 7;
    const int aRowL = wm * 32 + l7 + ((lane >> 3) & 1) * 8;
    const int aKwL  = (lane >> 4) * 4;
    uint32_t aLd0 = smA + (aRowL * BKW + aKwL) * 4;
    uint32_t aLd1 = aLd0 + 16 * BKW * 4;
    const int bRowL = wn * 32 + l7 + (lane >> 4) * 8;
    const int bKwL  = ((lane >> 3) & 1) * 4;
    uint32_t bg0 = smB + (bRowL * BKW + bKwL) * 4;
    uint32_t bg1 = bg0 + 16 * BKW * 4;
    uint32_t bu0 = bg0 + 64 * BKW * 4;
    uint32_t bu1 = bg1 + 64 * BKW * 4;

    float dg[2][4][4], du[2][4][4];
#pragma unroll
    for (int a = 0; a < 2; a++)
#pragma unroll
        for (int b = 0; b < 4; b++)
#pragma unroll
            for (int c = 0; c < 4; c++) { dg[a][b][c] = 0.f; du[a][b][c] = 0.f; }

#define G1_LOAD(j)                                                             \
    {                                                                          \
        const uint32_t so = ((j) & 3) * stB;                                   \
        const int k0 = (j) * BK;                                               \
        cp16(aDst0 + so, aSrc0 + k0); cp16(aDst1 + so, aSrc1 + k0);            \
        cp16(bgDst + so, bgSrc + k0); cp16(buDst + so, buSrc + k0);            \
    }

    const int NK = H / BK;  // 64
    G1_LOAD(0); cpcommit();
    G1_LOAD(1); cpcommit();
    G1_LOAD(2); cpcommit();
    cpwait2();
    __syncthreads();

    for (int it = 0; it < NK; ++it) {
        const int jl = it + 3;
        if (jl < NK) G1_LOAD(jl);
        cpcommit();
        const uint32_t so = (it & 3) * stB;

        uint32_t af[2][2][4];
        ldsm4(af[0][0], aLd0 + so);
        ldsm4(af[0][1], aLd1 + so);
        ldsm4(af[1][0], aLd0 + so + 32);
        ldsm4(af[1][1], aLd1 + so + 32);

        uint32_t bf[2][4];
        ldsm4(bf[0], bg0 + so); ldsm4(bf[1], bg0 + so + 32);
#pragma unroll
        for (int ks = 0; ks < 2; ks++) {
            mma16(dg[0][0], af[ks][0], bf[ks]);     mma16(dg[1][0], af[ks][1], bf[ks]);
            mma16(dg[0][1], af[ks][0], bf[ks] + 2); mma16(dg[1][1], af[ks][1], bf[ks] + 2);
        }
        ldsm4(bf[0], bg1 + so); ldsm4(bf[1], bg1 + so + 32);
#pragma unroll
        for (int ks = 0; ks < 2; ks++) {
            mma16(dg[0][2], af[ks][0], bf[ks]);     mma16(dg[1][2], af[ks][1], bf[ks]);
            mma16(dg[0][3], af[ks][0], bf[ks] + 2); mma16(dg[1][3], af[ks][1], bf[ks] + 2);
        }
        ldsm4(bf[0], bu0 + so); ldsm4(bf[1], bu0 + so + 32);
#pragma unroll
        for (int ks = 0; ks < 2; ks++) {
            mma16(du[0][0], af[ks][0], bf[ks]);     mma16(du[1][0], af[ks][1], bf[ks]);
            mma16(du[0][1], af[ks][0], bf[ks] + 2); mma16(du[1][1], af[ks][1], bf[ks] + 2);
        }
        ldsm4(bf[0], bu1 + so); ldsm4(bf[1], bu1 + so + 32);
#pragma unroll
        for (int ks = 0; ks < 2; ks++) {
            mma16(du[0][2], af[ks][0], bf[ks]);     mma16(du[1][2], af[ks][1], bf[ks]);
            mma16(du[0][3], af[ks][0], bf[ks] + 2); mma16(du[1][3], af[ks][1], bf[ks] + 2);
        }

        cpwait2();
        __syncthreads();
    }
#undef G1_LOAD

    // epilogue: SwiGLU -> g_h16
#pragma unroll
    for (int mi = 0; mi < 2; mi++) {
#pragma unroll
        for (int p = 0; p < 2; p++) {
            int rl = wm * 32 + mi * 16 + g + p * 8;
            if (m0 + rl < cnt) {
                size_t rb = (size_t)(base + m0 + rl) * IDIM + n0;
#pragma unroll
                for (int ni = 0; ni < 4; ni++) {
                    int col = wn * 32 + ni * 8 + t * 2;
                    float g0 = dg[mi][ni][p * 2], g1 = dg[mi][ni][p * 2 + 1];
                    float u0 = du[mi][ni][p * 2], u1 = du[mi][ni][p * 2 + 1];
                    float h0 = g0 / (1.f + expf(-g0)) * u0;
                    float h1 = g1 / (1.f + expf(-g1)) * u1;
                    __half2 hv = __floats2half2_rn(h0, h1);
                    *(__half2*)(g_h16 + rb + col) = hv;
                }
            }
        }
    }
}

// ---------------- K5: fp16 down GEMM (BN2=128, R14 body) + weighted atomic combine ----------------
__global__ void __launch_bounds__(256, 2) k_gemm2(float* __restrict__ out) {
    const int e   = blockIdx.z;
    const int cnt = g_cnt[e];
    const int m0  = blockIdx.y * BM;
    if (m0 >= cnt) return;
    const int n0   = blockIdx.x * BN2;
    const int base = g_base[e];

    extern __shared__ uint32_t sm[];
    const int STW = 2 * 128 * BKW;
    const uint32_t stB = STW * 4;

    const int tid  = threadIdx.x;
    const int lane = tid & 31;
    const int warp = tid >> 5;
    const int wm = warp & 3, wn = warp >> 2;
    const int g = lane >> 2, t = lane & 3;
    const int q = tid & 3, r0 = tid >> 2;

    int gr0 = m0 + r0;      if (gr0 > cnt - 1) gr0 = cnt - 1;
    int gr1 = m0 + r0 + 64; if (gr1 > cnt - 1) gr1 = cnt - 1;
    const __half* aSrc0 = g_h16 + (size_t)(base + gr0) * IDIM + q * 8;
    const __half* aSrc1 = g_h16 + (size_t)(base + gr1) * IDIM + q * 8;
    const __half* wb = g_wdn16 + (size_t)e * H * IDIM;
    const __half* bSrc0 = wb + (size_t)(n0 + r0) * IDIM + q * 8;
    const __half* bSrc1 = wb + (size_t)(n0 + 64 + r0) * IDIM + q * 8;

    const uint32_t smA = (uint32_t)__cvta_generic_to_shared(sm);
    const uint32_t smB = smA + 128 * BKW * 4;
    uint32_t aDst0 = smA + (r0 * BKW + q * 4) * 4;
    uint32_t aDst1 = smA + ((r0 + 64) * BKW + q * 4) * 4;
    uint32_t bDst0 = smB + (r0 * BKW + q * 4) * 4;
    uint32_t bDst1 = smB + ((r0 + 64) * BKW + q * 4) * 4;

    const int l7 = lane & 7;
    const int aRowL = wm * 32 + l7 + ((lane >> 3) & 1) * 8;
    const int aKwL  = (lane >> 4) * 4;
    uint32_t aLd0 = smA + (aRowL * BKW + aKwL) * 4;
    uint32_t aLd1 = aLd0 + 16 * BKW * 4;
    const int bRowL = wn * 64 + l7 + (lane >> 4) * 8;
    const int bKwL  = ((lane >> 3) & 1) * 4;
    uint32_t b0 = smB + (bRowL * BKW + bKwL) * 4;
    uint32_t b1 = b0 + 16 * BKW * 4;
    uint32_t b2 = b0 + 32 * BKW * 4;
    uint32_t b3 = b0 + 48 * BKW * 4;

    float d[2][8][4];
#pragma unroll
    for (int a = 0; a < 2; a++)
#pragma unroll
        for (int b = 0; b < 8; b++)
#pragma unroll
            for (int c = 0; c < 4; c++) d[a][b][c] = 0.f;

#define G2_LOAD(j)                                                             \
    {                                                                          \
        const uint32_t so = ((j) & 3) * stB;                                   \
        const int k0 = (j) * BK;                                               \
        cp16(aDst0 + so, aSrc0 + k0); cp16(aDst1 + so, aSrc1 + k0);            \
        cp16(bDst0 + so, bSrc0 + k0); cp16(bDst1 + so, bSrc1 + k0);            \
    }

    const int NK = IDIM / BK;  // 88
    G2_LOAD(0); cpcommit();
    G2_LOAD(1); cpcommit();
    G2_LOAD(2); cpcommit();
    cpwait2();
    __syncthreads();

    for (int it = 0; it < NK; ++it) {
        const int jl = it + 3;
        if (jl < NK) G2_LOAD(jl);
        cpcommit();
        const uint32_t so = (it & 3) * stB;

        uint32_t af[2][2][4];
        ldsm4(af[0][0], aLd0 + so);
        ldsm4(af[0][1], aLd1 + so);
        ldsm4(af[1][0], aLd0 + so + 32);
        ldsm4(af[1][1], aLd1 + so + 32);

        uint32_t bf[2][4];
        ldsm4(bf[0], b0 + so); ldsm4(bf[1], b0 + so + 32);
#pragma unroll
        for (int ks = 0; ks < 2; ks++) {
            mma16(d[0][0], af[ks][0], bf[ks]);     mma16(d[1][0], af[ks][1], bf[ks]);
            mma16(d[0][1], af[ks][0], bf[ks] + 2); mma16(d[1][1], af[ks][1], bf[ks] + 2);
        }
        ldsm4(bf[0], b1 + so); ldsm4(bf[1], b1 + so + 32);
#pragma unroll
        for (int ks = 0; ks < 2; ks++) {
            mma16(d[0][2], af[ks][0], bf[ks]);     mma16(d[1][2], af[ks][1], bf[ks]);
            mma16(d[0][3], af[ks][0], bf[ks] + 2); mma16(d[1][3], af[ks][1], bf[ks] + 2);
        }
        ldsm4(bf[0], b2 + so); ldsm4(bf[1], b2 + so + 32);
#pragma unroll
        for (int ks = 0; ks < 2; ks++) {
            mma16(d[0][4], af[ks][0], bf[ks]);     mma16(d[1][4], af[ks][1], bf[ks]);
            mma16(d[0][5], af[ks][0], bf[ks] + 2); mma16(d[1][5], af[ks][1], bf[ks] + 2);
        }
        ldsm4(bf[0], b3 + so); ldsm4(bf[1], b3 + so + 32);
#pragma unroll
        for (int ks = 0; ks < 2; ks++) {
            mma16(d[0][6], af[ks][0], bf[ks]);     mma16(d[1][6], af[ks][1], bf[ks]);
            mma16(d[0][7], af[ks][0], bf[ks] + 2); mma16(d[1][7], af[ks][1], bf[ks] + 2);
        }

        cpwait2();
        __syncthreads();
    }
#undef G2_LOAD

#pragma unroll
    for (int mi = 0; mi < 2; mi++) {
#pragma unroll
        for (int p = 0; p < 2; p++) {
            int rl = wm * 32 + mi * 16 + g + p * 8;
            if (m0 + rl < cnt) {
                int tok = g_list[e * T + m0 + rl];
                float w = g_wgt[e * T + m0 + rl];
                float* op = out + (size_t)tok * H + n0 + wn * 64;
#pragma unroll
                for (int ni = 0; ni < 8; ni++) {
                    int col = ni * 8 + t * 2;
                    atomicAdd(op + col,     w * d[mi][ni][p * 2]);
                    atomicAdd(op + col + 1, w * d[mi][ni][p * 2 + 1]);
                }
            }
        }
    }
}

// ---------------- launch ----------------
extern "C" void kernel_launch(void* const* d_in, const int* in_sizes, int n_in,
                              void* d_out, int out_size) {
    const float* x      = (const float*)d_in[0];
    const float* wg1    = (const float*)d_in[1];
    const float* wg2    = (const float*)d_in[2];
    const float* w_up   = (const float*)d_in[3];
    const float* w_down = (const float*)d_in[4];
    float* out = (float*)d_out;

    const int smem1 = NST * (2 * 128 * BKW) * 4;   // 81920
    const int smem2 = NST * (2 * 128 * BKW) * 4;   // 81920
    cudaFuncSetAttribute(k_gemm1, cudaFuncAttributeMaxDynamicSharedMemorySize, smem1);
    cudaFuncSetAttribute(k_gemm2, cudaFuncAttributeMaxDynamicSharedMemorySize, smem2);

    k_cvt<<<1184, 256>>>(x, w_up, w_down, out);                 // 1
    k_router<<<T / 64, 256>>>(x, wg1);                          // 2
    k_topk<<<T / 8, 256>>>(wg2);                                // 3 (incl. prefix)
    k_gemm1<<<dim3(IDIM / BN, MAXMT, NE), 256, smem1>>>();      // 4 (ncu slot)
    k_gemm2<<<dim3(H / BN2, MAXMT, NE), 256, smem2>>>(out);     // 5
}

// round 17
// speedup vs baseline: 1.1406x; 1.0584x over previous
#include <cuda_runtime.h>
#include <cuda_fp16.h>
#include <cstdint>
#include <math.h>

#define T 8192
#define H 2048
#define IDIM 2816
#define NE 16
#define R1 128

#define NX   ((size_t)T * H)
#define NUP  ((size_t)NE * 2 * IDIM * H)
#define NDN  ((size_t)NE * H * IDIM)
#define NOUT ((size_t)T * H)

#define BM 128
#define BN 64      // gemm1 N tile (gate; up mirrored)
#define BN2 128    // gemm2 N tile
#define BK 32      // halves per K slab (2 x k16 mma)
#define BKW 20     // padded words per 32-half row (conflict-free LDSM phases)
#define NST 4      // pipeline stages
#define MAXMT 16   // max m-tiles per expert (2048 tokens; counts are 1024±31)

// ---------------- device scratch (static) ----------------
__device__ __half g_x16[NX];
__device__ __half g_wup16[NUP];
__device__ __half g_wdn16[NDN];
__device__ float  g_tanh[(size_t)T * R1];
__device__ int    g_list[NE * T];
__device__ float  g_wgt[NE * T];
__device__ int    g_cnt[NE];
__device__ int    g_base[NE];
__device__ int    g_done;
__device__ __half g_h16[(size_t)(2 * T + 128) * IDIM];

// ---------------- helpers ----------------
__device__ __forceinline__ void mma16(float* d, const uint32_t* a, const uint32_t* b) {
    asm volatile(
        "mma.sync.aligned.m16n8k16.row.col.f32.f16.f16.f32 "
        "{%0,%1,%2,%3},{%4,%5,%6,%7},{%8,%9},{%0,%1,%2,%3};\n"
        : "+f"(d[0]), "+f"(d[1]), "+f"(d[2]), "+f"(d[3])
        : "r"(a[0]), "r"(a[1]), "r"(a[2]), "r"(a[3]), "r"(b[0]), "r"(b[1]));
}
__device__ __forceinline__ void ldsm4(uint32_t* r, uint32_t a) {
    asm volatile("ldmatrix.sync.aligned.m8n8.x4.shared.b16 {%0,%1,%2,%3}, [%4];"
        : "=r"(r[0]), "=r"(r[1]), "=r"(r[2]), "=r"(r[3]) : "r"(a));
}
__device__ __forceinline__ void cp16(uint32_t dst, const void* src) {
    asm volatile("cp.async.cg.shared.global [%0], [%1], 16;\n" :: "r"(dst), "l"(src));
}
__device__ __forceinline__ void cpcommit() { asm volatile("cp.async.commit_group;\n" ::); }
__device__ __forceinline__ void cpwait2()  { asm volatile("cp.async.wait_group 2;\n" ::); }

// ---------------- K-cvt: fp32 -> fp16 operands (8 floats/iter); zero out ----------------
__global__ void __launch_bounds__(256) k_cvt(const float* __restrict__ x,
                                             const float* __restrict__ wup,
                                             const float* __restrict__ wdn,
                                             float* __restrict__ out) {
    const size_t X8 = NX / 8, U8 = NUP / 8, D8 = NDN / 8, O8 = NOUT / 8;
    const size_t NT = X8 + U8 + D8 + O8;
    const size_t stride = (size_t)gridDim.x * blockDim.x;
    for (size_t i = (size_t)blockIdx.x * blockDim.x + threadIdx.x; i < NT; i += stride) {
        const float4* src; __half* dst; size_t off;
        if (i < X8)                { src = (const float4*)x;   dst = g_x16;   off = i; }
        else if (i < X8 + U8)      { src = (const float4*)wup; dst = g_wup16; off = i - X8; }
        else if (i < X8 + U8 + D8) { src = (const float4*)wdn; dst = g_wdn16; off = i - X8 - U8; }
        else {
            size_t o = (i - X8 - U8 - D8) * 2;
            float4 z = make_float4(0.f, 0.f, 0.f, 0.f);
            ((float4*)out)[o] = z; ((float4*)out)[o + 1] = z;
            continue;
        }
        float4 v0 = __ldg(src + off * 2);
        float4 v1 = __ldg(src + off * 2 + 1);
        __half2 a = __floats2half2_rn(v0.x, v0.y);
        __half2 b = __floats2half2_rn(v0.z, v0.w);
        __half2 c = __floats2half2_rn(v1.x, v1.y);
        __half2 d = __floats2half2_rn(v1.z, v1.w);
        uint4 pk = make_uint4(*(uint32_t*)&a, *(uint32_t*)&b, *(uint32_t*)&c, *(uint32_t*)&d);
        *(uint4*)(dst + off * 8) = pk;
    }
}

// ---------------- K1: router layer 1 (fp32 SIMT GEMM + tanh), 64 tokens/block ----------------
// (also zeroes expert counters — strictly before k_topk on the same stream)
__global__ void __launch_bounds__(256) k_router(const float* __restrict__ x,
                                                const float* __restrict__ wg1) {
    if (blockIdx.x == 0 && threadIdx.x < NE) g_cnt[threadIdx.x] = 0;
    __shared__ float As[16][68];
    __shared__ float Bs[16][132];
    const int m0  = blockIdx.x * 64;
    const int tid = threadIdx.x;
    const int r0  = (tid >> 4) * 4;
    const int c0  = (tid & 15) * 8;

    float acc[4][8];
#pragma unroll
    for (int r = 0; r < 4; r++)
#pragma unroll
        for (int c = 0; c < 8; c++) acc[r][c] = 0.f;

    for (int k0 = 0; k0 < H; k0 += 16) {
        {
            int row = tid >> 2, q = tid & 3;
            float4 v = *(const float4*)(x + (size_t)(m0 + row) * H + k0 + q * 4);
            As[q * 4 + 0][row] = v.x; As[q * 4 + 1][row] = v.y;
            As[q * 4 + 2][row] = v.z; As[q * 4 + 3][row] = v.w;
        }
#pragma unroll
        for (int i = 0; i < 2; i++) {
            int lin = tid + i * 256, n = lin >> 2, q = lin & 3;
            float4 v = *(const float4*)(wg1 + (size_t)n * H + k0 + q * 4);
            Bs[q * 4 + 0][n] = v.x; Bs[q * 4 + 1][n] = v.y;
            Bs[q * 4 + 2][n] = v.z; Bs[q * 4 + 3][n] = v.w;
        }
        __syncthreads();
#pragma unroll
        for (int kk = 0; kk < 16; kk++) {
            float a[4], b[8];
            *(float4*)a       = *(const float4*)&As[kk][r0];
            *(float4*)b       = *(const float4*)&Bs[kk][c0];
            *(float4*)(b + 4) = *(const float4*)&Bs[kk][c0 + 4];
#pragma unroll
            for (int r = 0; r < 4; r++)
#pragma unroll
                for (int c = 0; c < 8; c++) acc[r][c] += a[r] * b[c];
        }
        __syncthreads();
    }
#pragma unroll
    for (int r = 0; r < 4; r++)
#pragma unroll
        for (int c = 0; c < 8; c++)
            g_tanh[(size_t)(m0 + r0 + r) * R1 + c0 + c] = tanhf(acc[r][c]);
}

// ---------------- K2: router layer 2 + top-2 + routing tables + prefix ----------------
__global__ void k_topk(const float* __restrict__ wg2) {
    const int tok  = blockIdx.x * 8 + (threadIdx.x >> 5);
    const int lane = threadIdx.x & 31;
    float acc[NE];
#pragma unroll
    for (int e = 0; e < NE; e++) acc[e] = 0.f;
    const float* tv = g_tanh + (size_t)tok * R1;
#pragma unroll
    for (int j = 0; j < 4; j++) {
        float v = tv[lane + 32 * j];
#pragma unroll
        for (int e = 0; e < NE; e++) acc[e] += v * __ldg(&wg2[e * R1 + lane + 32 * j]);
    }
#pragma unroll
    for (int e = 0; e < NE; e++) {
        acc[e] += __shfl_xor_sync(0xffffffffu, acc[e], 16);
        acc[e] += __shfl_xor_sync(0xffffffffu, acc[e], 8);
        acc[e] += __shfl_xor_sync(0xffffffffu, acc[e], 4);
        acc[e] += __shfl_xor_sync(0xffffffffu, acc[e], 2);
        acc[e] += __shfl_xor_sync(0xffffffffu, acc[e], 1);
    }
    if (lane == 0) {
        int i1 = 0; float v1 = acc[0];
#pragma unroll
        for (int e = 1; e < NE; e++) if (acc[e] > v1) { v1 = acc[e]; i1 = e; }
        int i2 = -1; float v2 = -3.4e38f;
#pragma unroll
        for (int e = 0; e < NE; e++) if (e != i1 && acc[e] > v2) { v2 = acc[e]; i2 = e; }
        float w1 = 1.f / (1.f + expf(v2 - v1));
        float w2 = 1.f / (1.f + expf(v1 - v2));
        int s1 = atomicAdd(&g_cnt[i1], 1);
        g_list[i1 * T + s1] = tok; g_wgt[i1 * T + s1] = w1;
        int s2 = atomicAdd(&g_cnt[i2], 1);
        g_list[i2 * T + s2] = tok; g_wgt[i2 * T + s2] = w2;
    }
    __syncthreads();
    if (threadIdx.x == 0) {
        __threadfence();
        int d = atomicAdd(&g_done, 1);
        if (d == gridDim.x - 1) {
            int s = 0;
            for (int e = 0; e < NE; e++) {
                int c = atomicAdd(&g_cnt[e], 0);
                g_base[e] = s; s += c;
            }
            atomicExch(&g_done, 0);
        }
    }
}

// ---------------- K4: fp16 gate+up GEMM fused with SwiGLU (R14 body) ----------------
__global__ void __launch_bounds__(256, 2) k_gemm1() {
    const int e   = blockIdx.z;
    const int cnt = g_cnt[e];
    const int m0  = blockIdx.y * BM;
    if (m0 >= cnt) return;
    const int n0   = blockIdx.x * BN;
    const int base = g_base[e];

    extern __shared__ uint32_t sm[];
    const int STW = 2 * 128 * BKW;
    const uint32_t stB = STW * 4;

    const int tid  = threadIdx.x;
    const int lane = tid & 31;
    const int warp = tid >> 5;
    const int wm = warp & 3, wn = warp >> 2;
    const int g = lane >> 2, t = lane & 3;
    const int q = tid & 3, r0 = tid >> 2;

    int gr0 = m0 + r0;      if (gr0 > cnt - 1) gr0 = cnt - 1;
    int gr1 = m0 + r0 + 64; if (gr1 > cnt - 1) gr1 = cnt - 1;
    const __half* aSrc0 = g_x16 + (size_t)g_list[e * T + gr0] * H + q * 8;
    const __half* aSrc1 = g_x16 + (size_t)g_list[e * T + gr1] * H + q * 8;
    const __half* wb = g_wup16 + (size_t)e * 2 * IDIM * H;
    const __half* bgSrc = wb + (size_t)(n0 + r0) * H + q * 8;
    const __half* buSrc = wb + (size_t)(IDIM + n0 + r0) * H + q * 8;

    const uint32_t smA = (uint32_t)__cvta_generic_to_shared(sm);
    const uint32_t smB = smA + 128 * BKW * 4;
    uint32_t aDst0 = smA + (r0 * BKW + q * 4) * 4;
    uint32_t aDst1 = smA + ((r0 + 64) * BKW + q * 4) * 4;
    uint32_t bgDst = smB + (r0 * BKW + q * 4) * 4;
    uint32_t buDst = smB + ((64 + r0) * BKW + q * 4) * 4;

    const int l7 = lane & 7;
    const int aRowL = wm * 32 + l7 + ((lane >> 3) & 1) * 8;
    const int aKwL  = (lane >> 4) * 4;
    uint32_t aLd0 = smA + (aRowL * BKW + aKwL) * 4;
    uint32_t aLd1 = aLd0 + 16 * BKW * 4;
    const int bRowL = wn * 32 + l7 + (lane >> 4) * 8;
    const int bKwL  = ((lane >> 3) & 1) * 4;
    uint32_t bg0 = smB + (bRowL * BKW + bKwL) * 4;
    uint32_t bg1 = bg0 + 16 * BKW * 4;
    uint32_t bu0 = bg0 + 64 * BKW * 4;
    uint32_t bu1 = bg1 + 64 * BKW * 4;

    float dg[2][4][4], du[2][4][4];
#pragma unroll
    for (int a = 0; a < 2; a++)
#pragma unroll
        for (int b = 0; b < 4; b++)
#pragma unroll
            for (int c = 0; c < 4; c++) { dg[a][b][c] = 0.f; du[a][b][c] = 0.f; }

#define G1_LOAD(j)                                                             \
    {                                                                          \
        const uint32_t so = ((j) & 3) * stB;                                   \
        const int k0 = (j) * BK;                                               \
        cp16(aDst0 + so, aSrc0 + k0); cp16(aDst1 + so, aSrc1 + k0);            \
        cp16(bgDst + so, bgSrc + k0); cp16(buDst + so, buSrc + k0);            \
    }

    const int NK = H / BK;  // 64
    G1_LOAD(0); cpcommit();
    G1_LOAD(1); cpcommit();
    G1_LOAD(2); cpcommit();
    cpwait2();
    __syncthreads();

    for (int it = 0; it < NK; ++it) {
        const int jl = it + 3;
        if (jl < NK) G1_LOAD(jl);
        cpcommit();
        const uint32_t so = (it & 3) * stB;

        uint32_t af[2][2][4];
        ldsm4(af[0][0], aLd0 + so);
        ldsm4(af[0][1], aLd1 + so);
        ldsm4(af[1][0], aLd0 + so + 32);
        ldsm4(af[1][1], aLd1 + so + 32);

        uint32_t bf[2][4];
        ldsm4(bf[0], bg0 + so); ldsm4(bf[1], bg0 + so + 32);
#pragma unroll
        for (int ks = 0; ks < 2; ks++) {
            mma16(dg[0][0], af[ks][0], bf[ks]);     mma16(dg[1][0], af[ks][1], bf[ks]);
            mma16(dg[0][1], af[ks][0], bf[ks] + 2); mma16(dg[1][1], af[ks][1], bf[ks] + 2);
        }
        ldsm4(bf[0], bg1 + so); ldsm4(bf[1], bg1 + so + 32);
#pragma unroll
        for (int ks = 0; ks < 2; ks++) {
            mma16(dg[0][2], af[ks][0], bf[ks]);     mma16(dg[1][2], af[ks][1], bf[ks]);
            mma16(dg[0][3], af[ks][0], bf[ks] + 2); mma16(dg[1][3], af[ks][1], bf[ks] + 2);
        }
        ldsm4(bf[0], bu0 + so); ldsm4(bf[1], bu0 + so + 32);
#pragma unroll
        for (int ks = 0; ks < 2; ks++) {
            mma16(du[0][0], af[ks][0], bf[ks]);     mma16(du[1][0], af[ks][1], bf[ks]);
            mma16(du[0][1], af[ks][0], bf[ks] + 2); mma16(du[1][1], af[ks][1], bf[ks] + 2);
        }
        ldsm4(bf[0], bu1 + so); ldsm4(bf[1], bu1 + so + 32);
#pragma unroll
        for (int ks = 0; ks < 2; ks++) {
            mma16(du[0][2], af[ks][0], bf[ks]);     mma16(du[1][2], af[ks][1], bf[ks]);
            mma16(du[0][3], af[ks][0], bf[ks] + 2); mma16(du[1][3], af[ks][1], bf[ks] + 2);
        }

        cpwait2();
        __syncthreads();
    }
#undef G1_LOAD

    // epilogue: SwiGLU -> g_h16
#pragma unroll
    for (int mi = 0; mi < 2; mi++) {
#pragma unroll
        for (int p = 0; p < 2; p++) {
            int rl = wm * 32 + mi * 16 + g + p * 8;
            if (m0 + rl < cnt) {
                size_t rb = (size_t)(base + m0 + rl) * IDIM + n0;
#pragma unroll
                for (int ni = 0; ni < 4; ni++) {
                    int col = wn * 32 + ni * 8 + t * 2;
                    float g0 = dg[mi][ni][p * 2], g1 = dg[mi][ni][p * 2 + 1];
                    float u0 = du[mi][ni][p * 2], u1 = du[mi][ni][p * 2 + 1];
                    float h0 = g0 / (1.f + expf(-g0)) * u0;
                    float h1 = g1 / (1.f + expf(-g1)) * u1;
                    __half2 hv = __floats2half2_rn(h0, h1);
                    *(__half2*)(g_h16 + rb + col) = hv;
                }
            }
        }
    }
}

// ---------------- K5: fp16 down GEMM (BN2=128, R14 body) + weighted atomic combine ----------------
__global__ void __launch_bounds__(256, 2) k_gemm2(float* __restrict__ out) {
    const int e   = blockIdx.z;
    const int cnt = g_cnt[e];
    const int m0  = blockIdx.y * BM;
    if (m0 >= cnt) return;
    const int n0   = blockIdx.x * BN2;
    const int base = g_base[e];

    extern __shared__ uint32_t sm[];
    const int STW = 2 * 128 * BKW;
    const uint32_t stB = STW * 4;

    const int tid  = threadIdx.x;
    const int lane = tid & 31;
    const int warp = tid >> 5;
    const int wm = warp & 3, wn = warp >> 2;
    const int g = lane >> 2, t = lane & 3;
    const int q = tid & 3, r0 = tid >> 2;

    int gr0 = m0 + r0;      if (gr0 > cnt - 1) gr0 = cnt - 1;
    int gr1 = m0 + r0 + 64; if (gr1 > cnt - 1) gr1 = cnt - 1;
    const __half* aSrc0 = g_h16 + (size_t)(base + gr0) * IDIM + q * 8;
    const __half* aSrc1 = g_h16 + (size_t)(base + gr1) * IDIM + q * 8;
    const __half* wb = g_wdn16 + (size_t)e * H * IDIM;
    const __half* bSrc0 = wb + (size_t)(n0 + r0) * IDIM + q * 8;
    const __half* bSrc1 = wb + (size_t)(n0 + 64 + r0) * IDIM + q * 8;

    const uint32_t smA = (uint32_t)__cvta_generic_to_shared(sm);
    const uint32_t smB = smA + 128 * BKW * 4;
    uint32_t aDst0 = smA + (r0 * BKW + q * 4) * 4;
    uint32_t aDst1 = smA + ((r0 + 64) * BKW + q * 4) * 4;
    uint32_t bDst0 = smB + (r0 * BKW + q * 4) * 4;
    uint32_t bDst1 = smB + ((r0 + 64) * BKW + q * 4) * 4;

    const int l7 = lane & 7;
    const int aRowL = wm * 32 + l7 + ((lane >> 3) & 1) * 8;
    const int aKwL  = (lane >> 4) * 4;
    uint32_t aLd0 = smA + (aRowL * BKW + aKwL) * 4;
    uint32_t aLd1 = aLd0 + 16 * BKW * 4;
    const int bRowL = wn * 64 + l7 + (lane >> 4) * 8;
    const int bKwL  = ((lane >> 3) & 1) * 4;
    uint32_t b0 = smB + (bRowL * BKW + bKwL) * 4;
    uint32_t b1 = b0 + 16 * BKW * 4;
    uint32_t b2 = b0 + 32 * BKW * 4;
    uint32_t b3 = b0 + 48 * BKW * 4;

    float d[2][8][4];
#pragma unroll
    for (int a = 0; a < 2; a++)
#pragma unroll
        for (int b = 0; b < 8; b++)
#pragma unroll
            for (int c = 0; c < 4; c++) d[a][b][c] = 0.f;

#define G2_LOAD(j)                                                             \
    {                                                                          \
        const uint32_t so = ((j) & 3) * stB;                                   \
        const int k0 = (j) * BK;                                               \
        cp16(aDst0 + so, aSrc0 + k0); cp16(aDst1 + so, aSrc1 + k0);            \
        cp16(bDst0 + so, bSrc0 + k0); cp16(bDst1 + so, bSrc1 + k0);            \
    }

    const int NK = IDIM / BK;  // 88
    G2_LOAD(0); cpcommit();
    G2_LOAD(1); cpcommit();
    G2_LOAD(2); cpcommit();
    cpwait2();
    __syncthreads();

    for (int it = 0; it < NK; ++it) {
        const int jl = it + 3;
        if (jl < NK) G2_LOAD(jl);
        cpcommit();
        const uint32_t so = (it & 3) * stB;

        uint32_t af[2][2][4];
        ldsm4(af[0][0], aLd0 + so);
        ldsm4(af[0][1], aLd1 + so);
        ldsm4(af[1][0], aLd0 + so + 32);
        ldsm4(af[1][1], aLd1 + so + 32);

        uint32_t bf[2][4];
        ldsm4(bf[0], b0 + so); ldsm4(bf[1], b0 + so + 32);
#pragma unroll
        for (int ks = 0; ks < 2; ks++) {
            mma16(d[0][0], af[ks][0], bf[ks]);     mma16(d[1][0], af[ks][1], bf[ks]);
            mma16(d[0][1], af[ks][0], bf[ks] + 2); mma16(d[1][1], af[ks][1], bf[ks] + 2);
        }
        ldsm4(bf[0], b1 + so); ldsm4(bf[1], b1 + so + 32);
#pragma unroll
        for (int ks = 0; ks < 2; ks++) {
            mma16(d[0][2], af[ks][0], bf[ks]);     mma16(d[1][2], af[ks][1], bf[ks]);
            mma16(d[0][3], af[ks][0], bf[ks] + 2); mma16(d[1][3], af[ks][1], bf[ks] + 2);
        }
        ldsm4(bf[0], b2 + so); ldsm4(bf[1], b2 + so + 32);
#pragma unroll
        for (int ks = 0; ks < 2; ks++) {
            mma16(d[0][4], af[ks][0], bf[ks]);     mma16(d[1][4], af[ks][1], bf[ks]);
            mma16(d[0][5], af[ks][0], bf[ks] + 2); mma16(d[1][5], af[ks][1], bf[ks] + 2);
        }
        ldsm4(bf[0], b3 + so); ldsm4(bf[1], b3 + so + 32);
#pragma unroll
        for (int ks = 0; ks < 2; ks++) {
            mma16(d[0][6], af[ks][0], bf[ks]);     mma16(d[1][6], af[ks][1], bf[ks]);
            mma16(d[0][7], af[ks][0], bf[ks] + 2); mma16(d[1][7], af[ks][1], bf[ks] + 2);
        }

        cpwait2();
        __syncthreads();
    }
#undef G2_LOAD

#pragma unroll
    for (int mi = 0; mi < 2; mi++) {
#pragma unroll
        for (int p = 0; p < 2; p++) {
            int rl = wm * 32 + mi * 16 + g + p * 8;
            if (m0 + rl < cnt) {
                int tok = g_list[e * T + m0 + rl];
                float w = g_wgt[e * T + m0 + rl];
                float* op = out + (size_t)tok * H + n0 + wn * 64;
#pragma unroll
                for (int ni = 0; ni < 8; ni++) {
                    int col = ni * 8 + t * 2;
                    atomicAdd(op + col,     w * d[mi][ni][p * 2]);
                    atomicAdd(op + col + 1, w * d[mi][ni][p * 2 + 1]);
                }
            }
        }
    }
}

// ---------------- launch ----------------
extern "C" void kernel_launch(void* const* d_in, const int* in_sizes, int n_in,
                              void* d_out, int out_size) {
    const float* x      = (const float*)d_in[0];
    const float* wg1    = (const float*)d_in[1];
    const float* wg2    = (const float*)d_in[2];
    const float* w_up   = (const float*)d_in[3];
    const float* w_down = (const float*)d_in[4];
    float* out = (float*)d_out;

    const int smem1 = NST * (2 * 128 * BKW) * 4;   // 81920
    const int smem2 = NST * (2 * 128 * BKW) * 4;   // 81920
    cudaFuncSetAttribute(k_gemm1, cudaFuncAttributeMaxDynamicSharedMemorySize, smem1);
    cudaFuncSetAttribute(k_gemm2, cudaFuncAttributeMaxDynamicSharedMemorySize, smem2);

    // fork/join objects (host-side; created per call, not destroyed mid-capture)
    cudaStream_t s2;
    cudaStreamCreateWithFlags(&s2, cudaStreamNonBlocking);
    cudaEvent_t evFork, evJoin;
    cudaEventCreateWithFlags(&evFork, cudaEventDisableTiming);
    cudaEventCreateWithFlags(&evJoin, cudaEventDisableTiming);

    cudaEventRecord(evFork, 0);
    cudaStreamWaitEvent(s2, evFork, 0);
    k_router<<<T / 64, 256, 0, s2>>>(x, wg1);                   // side: router (+cnt zero)
    k_topk<<<T / 8, 256, 0, s2>>>(wg2);                         // side: topk + prefix
    cudaEventRecord(evJoin, s2);

    k_cvt<<<1036, 256>>>(x, w_up, w_down, out);                 // main: cvt (7 blocks/SM)

    cudaStreamWaitEvent(0, evJoin, 0);
    k_gemm1<<<dim3(IDIM / BN, MAXMT, NE), 256, smem1>>>();      // main (ncu slot)
    k_gemm2<<<dim3(H / BN2, MAXMT, NE), 256, smem2>>>(out);     // main
}